// round 9
// baseline (speedup 1.0000x reference)
#include <cuda_runtime.h>
#include <cstring>

// Problem constants (fixed shapes per reference)
#define N_NODES 100000
#define N_EDGES 1600000
#define IN_F    128
#define OUT_F   256

#define SCAN_BLK 1024
#define N_SCAN_BLKS ((N_NODES + SCAN_BLK - 1) / SCAN_BLK)   // 98

// ---- static device scratch (no allocation allowed) ----
__device__ __align__(16) float g_h[(size_t)N_NODES * IN_F];   // aggregated features (with self loop), 51.2 MB
__device__ __align__(16) int g_deg[N_NODES];
__device__ int g_off[N_NODES + 1];
__device__ int g_cursor[N_NODES];
__device__ int g_srcs[N_EDGES];                               // edge sources bucketed by dst, 6.4 MB
__device__ int g_bsums[256];

// ------------------------------------------------------------------
// K1: zero degree counters (int4 stores; N_NODES % 4 == 0)
// ------------------------------------------------------------------
__global__ void k_zero_deg() {
    int i = blockIdx.x * blockDim.x + threadIdx.x;
    if (i < N_NODES / 4)
        ((int4*)g_deg)[i] = make_int4(0, 0, 0, 0);
}

// ------------------------------------------------------------------
// K2: histogram of dst (int4-vectorized: 4 edges per thread)
// N_EDGES is divisible by 4.
// ------------------------------------------------------------------
__global__ void k_count(const int* __restrict__ dst) {
    int q = blockIdx.x * blockDim.x + threadIdx.x;
    if (q < N_EDGES / 4) {
        int4 d = __ldg(&((const int4*)dst)[q]);
        atomicAdd(&g_deg[d.x], 1);
        atomicAdd(&g_deg[d.y], 1);
        atomicAdd(&g_deg[d.z], 1);
        atomicAdd(&g_deg[d.w], 1);
    }
}

// ------------------------------------------------------------------
// K3a: per-block exclusive scan of deg -> off (partial), block totals -> bsums
// ------------------------------------------------------------------
__global__ void k_scan_blocks() {
    __shared__ int sh[SCAN_BLK];
    int t = threadIdx.x;
    int i = blockIdx.x * SCAN_BLK + t;
    int v = (i < N_NODES) ? g_deg[i] : 0;
    sh[t] = v;
    __syncthreads();
    #pragma unroll
    for (int ofs = 1; ofs < SCAN_BLK; ofs <<= 1) {
        int add = (t >= ofs) ? sh[t - ofs] : 0;
        __syncthreads();
        sh[t] += add;
        __syncthreads();
    }
    if (i < N_NODES) g_off[i] = sh[t] - v;   // exclusive partial
    if (t == SCAN_BLK - 1) g_bsums[blockIdx.x] = sh[t];
}

// ------------------------------------------------------------------
// K3b: single-block exclusive scan of the block sums
// ------------------------------------------------------------------
__global__ void k_scan_sums() {
    __shared__ int sh[128];
    int t = threadIdx.x;
    int v = (t < N_SCAN_BLKS) ? g_bsums[t] : 0;
    sh[t] = v;
    __syncthreads();
    #pragma unroll
    for (int ofs = 1; ofs < 128; ofs <<= 1) {
        int add = (t >= ofs) ? sh[t - ofs] : 0;
        __syncthreads();
        sh[t] += add;
        __syncthreads();
    }
    if (t < N_SCAN_BLKS) g_bsums[t] = sh[t] - v;   // exclusive
}

// ------------------------------------------------------------------
// K3c: add block offsets, init cursors, set sentinel
// ------------------------------------------------------------------
__global__ void k_scan_add() {
    int i = blockIdx.x * blockDim.x + threadIdx.x;
    if (i < N_NODES) {
        int o = g_off[i] + g_bsums[i >> 10];
        g_off[i] = o;
        g_cursor[i] = o;
    }
    if (i == 0) g_off[N_NODES] = N_EDGES;
}

// ------------------------------------------------------------------
// K4: bucket edge sources by dst (int4-vectorized)
// ------------------------------------------------------------------
__global__ void k_fill(const int* __restrict__ src, const int* __restrict__ dst) {
    int q = blockIdx.x * blockDim.x + threadIdx.x;
    if (q < N_EDGES / 4) {
        int4 s = __ldg(&((const int4*)src)[q]);
        int4 d = __ldg(&((const int4*)dst)[q]);
        g_srcs[atomicAdd(&g_cursor[d.x], 1)] = s.x;
        g_srcs[atomicAdd(&g_cursor[d.y], 1)] = s.y;
        g_srcs[atomicAdd(&g_cursor[d.z], 1)] = s.z;
        g_srcs[atomicAdd(&g_cursor[d.w], 1)] = s.w;
    }
}

// ------------------------------------------------------------------
// K5: gather-aggregate. One warp per node; lane owns a float4 chunk (128 f32 row).
// h[v] = features[v] + sum_{u in in-neighbors(v)} features[u]
// unroll-8: eight independent gathers in flight to hide L2 latency.
// ------------------------------------------------------------------
__global__ void k_aggregate(const float* __restrict__ feat) {
    int gw   = (blockIdx.x * blockDim.x + threadIdx.x) >> 5;
    int lane = threadIdx.x & 31;
    if (gw >= N_NODES) return;

    const float4* f4 = (const float4*)feat;
    float4 acc = __ldg(&f4[(size_t)gw * 32 + lane]);   // self loop

    int j = g_off[gw];
    const int e = g_off[gw + 1];
    for (; j + 7 < e; j += 8) {
        int u0 = g_srcs[j];
        int u1 = g_srcs[j + 1];
        int u2 = g_srcs[j + 2];
        int u3 = g_srcs[j + 3];
        int u4 = g_srcs[j + 4];
        int u5 = g_srcs[j + 5];
        int u6 = g_srcs[j + 6];
        int u7 = g_srcs[j + 7];
        float4 x0 = __ldg(&f4[(size_t)u0 * 32 + lane]);
        float4 x1 = __ldg(&f4[(size_t)u1 * 32 + lane]);
        float4 x2 = __ldg(&f4[(size_t)u2 * 32 + lane]);
        float4 x3 = __ldg(&f4[(size_t)u3 * 32 + lane]);
        float4 x4 = __ldg(&f4[(size_t)u4 * 32 + lane]);
        float4 x5 = __ldg(&f4[(size_t)u5 * 32 + lane]);
        float4 x6 = __ldg(&f4[(size_t)u6 * 32 + lane]);
        float4 x7 = __ldg(&f4[(size_t)u7 * 32 + lane]);
        acc.x += ((x0.x + x1.x) + (x2.x + x3.x)) + ((x4.x + x5.x) + (x6.x + x7.x));
        acc.y += ((x0.y + x1.y) + (x2.y + x3.y)) + ((x4.y + x5.y) + (x6.y + x7.y));
        acc.z += ((x0.z + x1.z) + (x2.z + x3.z)) + ((x4.z + x5.z) + (x6.z + x7.z));
        acc.w += ((x0.w + x1.w) + (x2.w + x3.w)) + ((x4.w + x5.w) + (x6.w + x7.w));
    }
    for (; j + 3 < e; j += 4) {
        int u0 = g_srcs[j];
        int u1 = g_srcs[j + 1];
        int u2 = g_srcs[j + 2];
        int u3 = g_srcs[j + 3];
        float4 x0 = __ldg(&f4[(size_t)u0 * 32 + lane]);
        float4 x1 = __ldg(&f4[(size_t)u1 * 32 + lane]);
        float4 x2 = __ldg(&f4[(size_t)u2 * 32 + lane]);
        float4 x3 = __ldg(&f4[(size_t)u3 * 32 + lane]);
        acc.x += (x0.x + x1.x) + (x2.x + x3.x);
        acc.y += (x0.y + x1.y) + (x2.y + x3.y);
        acc.z += (x0.z + x1.z) + (x2.z + x3.z);
        acc.w += (x0.w + x1.w) + (x2.w + x3.w);
    }
    for (; j < e; j++) {
        int u = g_srcs[j];
        float4 x = __ldg(&f4[(size_t)u * 32 + lane]);
        acc.x += x.x; acc.y += x.y; acc.z += x.z; acc.w += x.w;
    }
    ((float4*)g_h)[(size_t)gw * 32 + lane] = acc;
}

// ------------------------------------------------------------------
// K6: fp32 GEMM out[M,256] = h[M,128] @ W[128,256] + bias
// CTA tile 128x128, K chunked by 32, 256 threads, thread tile 8 rows x 8 cols
// (4 adjacent-column pairs) using packed fma.rn.f32x2 (FFMA2, 2x fp32 rate).
// Register-prefetch software pipeline: next K-chunk's global loads issue
// before the current chunk's FFMA2 stream and drain underneath it.
// ------------------------------------------------------------------
__global__ void __launch_bounds__(256) k_gemm(const float* __restrict__ W,
                                              const float* __restrict__ bias,
                                              float* __restrict__ out) {
    __shared__ __align__(16) float As[128][32];   // [row][k]
    __shared__ __align__(16) float Bs[32][128];   // [k][col]

    const int tid = threadIdx.x;
    const int tx  = tid & 15;    // column group
    const int ty  = tid >> 4;    // row group
    const int m0  = blockIdx.y * 128;
    const int n0  = blockIdx.x * 128;

    unsigned long long acc[8][4];
    #pragma unroll
    for (int i = 0; i < 8; i++)
        #pragma unroll
        for (int j = 0; j < 4; j++) acc[i][j] = 0ull;   // bit pattern of {0.f,0.f}

    // ---- prologue: fetch K-chunk 0 into registers ----
    float4 pa[4], pb[4];
    #pragma unroll
    for (int i = 0; i < 4; i++) {
        int l  = tid + 256 * i;
        int r  = l >> 3, ks = l & 7;       // A: 128 rows x 8 float4
        int row = m0 + r;
        pa[i] = (row < N_NODES)
              ? *(const float4*)&g_h[(size_t)row * 128 + ks * 4]
              : make_float4(0.f, 0.f, 0.f, 0.f);
        int k  = l >> 5, cs = l & 31;      // B: 32 k x 32 float4
        pb[i] = __ldg((const float4*)&W[(size_t)k * OUT_F + n0 + cs * 4]);
    }

    #pragma unroll
    for (int kk = 0; kk < 128; kk += 32) {
        // stage prefetched chunk into smem
        #pragma unroll
        for (int i = 0; i < 4; i++) {
            int l = tid + 256 * i;
            *(float4*)&As[l >> 3][(l & 7) * 4]  = pa[i];
            *(float4*)&Bs[l >> 5][(l & 31) * 4] = pb[i];
        }
        __syncthreads();

        // prefetch next chunk (overlaps with compute below)
        if (kk + 32 < 128) {
            #pragma unroll
            for (int i = 0; i < 4; i++) {
                int l  = tid + 256 * i;
                int r  = l >> 3, ks = l & 7;
                int row = m0 + r;
                pa[i] = (row < N_NODES)
                      ? *(const float4*)&g_h[(size_t)row * 128 + (kk + 32) + ks * 4]
                      : make_float4(0.f, 0.f, 0.f, 0.f);
                int k  = l >> 5, cs = l & 31;
                pb[i] = __ldg((const float4*)&W[(size_t)(kk + 32 + k) * OUT_F + n0 + cs * 4]);
            }
        }

        // compute on current chunk
        #pragma unroll
        for (int k = 0; k < 32; k++) {
            unsigned long long b[4];
            #pragma unroll
            for (int j = 0; j < 4; j++)
                b[j] = *(const unsigned long long*)&Bs[k][tx * 2 + 32 * j];
            #pragma unroll
            for (int i = 0; i < 8; i++) {
                float a = As[ty * 8 + i][k];
                unsigned long long a2;
                asm("mov.b64 %0, {%1, %1};" : "=l"(a2) : "r"(__float_as_uint(a)));
                #pragma unroll
                for (int j = 0; j < 4; j++)
                    asm("fma.rn.f32x2 %0, %1, %2, %0;"
                        : "+l"(acc[i][j]) : "l"(a2), "l"(b[j]));
            }
        }
        __syncthreads();
    }

    // epilogue: + bias, write float2 per (i,j)
    #pragma unroll
    for (int i = 0; i < 8; i++) {
        int row = m0 + ty * 8 + i;
        if (row >= N_NODES) continue;
        #pragma unroll
        for (int j = 0; j < 4; j++) {
            int c = n0 + tx * 2 + 32 * j;
            float2 bv = *(const float2*)&bias[c];
            float2 v;
            memcpy(&v, &acc[i][j], 8);
            v.x += bv.x;
            v.y += bv.y;
            *(float2*)&out[(size_t)row * OUT_F + c] = v;
        }
    }
}

// ------------------------------------------------------------------
extern "C" void kernel_launch(void* const* d_in, const int* in_sizes, int n_in,
                              void* d_out, int out_size) {
    const float* features = (const float*)d_in[0];
    const int*   src      = (const int*)d_in[1];
    const int*   dst      = (const int*)d_in[2];
    const float* weight   = (const float*)d_in[3];
    const float* bias     = (const float*)d_in[4];
    float*       out      = (float*)d_out;

    k_zero_deg   <<<(N_NODES / 4 + 255) / 256, 256>>>();
    k_count      <<<(N_EDGES / 4 + 255) / 256, 256>>>(dst);
    k_scan_blocks<<<N_SCAN_BLKS, SCAN_BLK>>>();
    k_scan_sums  <<<1, 128>>>();
    k_scan_add   <<<(N_NODES + 1023) / 1024, 1024>>>();
    k_fill       <<<(N_EDGES / 4 + 255) / 256, 256>>>(src, dst);
    k_aggregate  <<<(N_NODES * 32 + 255) / 256, 256>>>(features);

    dim3 ggrid(OUT_F / 128, (N_NODES + 127) / 128);   // (2, 782)
    k_gemm<<<ggrid, 256>>>(weight, bias, out);
}

// round 12
// speedup vs baseline: 1.4333x; 1.4333x over previous
#include <cuda_runtime.h>
#include <cstring>

// Problem constants (fixed shapes per reference)
#define N_NODES 100000
#define N_EDGES 1600000
#define IN_F    128
#define OUT_F   256

#define SCAN_BLK 1024
#define N_SCAN_BLKS ((N_NODES + SCAN_BLK - 1) / SCAN_BLK)   // 98

// ---- static device scratch (no allocation allowed) ----
__device__ __align__(16) float g_h[(size_t)N_NODES * IN_F];   // aggregated features, 51.2 MB
__device__ __align__(16) int g_deg[N_NODES];                  // zero-init by loader; re-zeroed each call
__device__ int g_off[N_NODES + 1];
__device__ int g_cursor[N_NODES];
__device__ int g_srcs[N_EDGES];                               // edge sources bucketed by dst, 6.4 MB
__device__ int g_bsums[256];

// ------------------------------------------------------------------
// K2: histogram of dst (int4-vectorized: 4 edges per thread)
// ------------------------------------------------------------------
__global__ void k_count(const int* __restrict__ dst) {
    int q = blockIdx.x * blockDim.x + threadIdx.x;
    if (q < N_EDGES / 4) {
        int4 d = __ldg(&((const int4*)dst)[q]);
        atomicAdd(&g_deg[d.x], 1);
        atomicAdd(&g_deg[d.y], 1);
        atomicAdd(&g_deg[d.z], 1);
        atomicAdd(&g_deg[d.w], 1);
    }
}

// ------------------------------------------------------------------
// K3a: per-block exclusive scan of deg -> off (partial), block totals -> bsums
// ------------------------------------------------------------------
__global__ void k_scan_blocks() {
    __shared__ int sh[SCAN_BLK];
    int t = threadIdx.x;
    int i = blockIdx.x * SCAN_BLK + t;
    int v = (i < N_NODES) ? g_deg[i] : 0;
    sh[t] = v;
    __syncthreads();
    #pragma unroll
    for (int ofs = 1; ofs < SCAN_BLK; ofs <<= 1) {
        int add = (t >= ofs) ? sh[t - ofs] : 0;
        __syncthreads();
        sh[t] += add;
        __syncthreads();
    }
    if (i < N_NODES) g_off[i] = sh[t] - v;   // exclusive partial
    if (t == SCAN_BLK - 1) g_bsums[blockIdx.x] = sh[t];
}

// ------------------------------------------------------------------
// K3b (fused): each block scans the <=98 block sums itself, adds its own
// base, inits cursors, zeroes g_deg for the next replay, sets sentinel.
// ------------------------------------------------------------------
__global__ void k_scan_add() {
    __shared__ int sb[128];
    __shared__ int s_base;
    int t = threadIdx.x;
    if (t < 128)
        sb[t] = (t < N_SCAN_BLKS) ? g_bsums[t] : 0;
    __syncthreads();
    #pragma unroll
    for (int ofs = 1; ofs < 128; ofs <<= 1) {
        int add = 0;
        if (t < 128 && t >= ofs) add = sb[t - ofs];
        __syncthreads();
        if (t < 128) sb[t] += add;
        __syncthreads();
    }
    if (t == 0) s_base = (blockIdx.x == 0) ? 0 : sb[blockIdx.x - 1];
    __syncthreads();

    int i = blockIdx.x * SCAN_BLK + t;
    if (i < N_NODES) {
        int o = g_off[i] + s_base;
        g_off[i] = o;
        g_cursor[i] = o;
        g_deg[i] = 0;          // reset histogram for next graph replay
    }
    if (i == 0) g_off[N_NODES] = N_EDGES;
}

// ------------------------------------------------------------------
// K4: bucket edge sources by dst (int4-vectorized)
// ------------------------------------------------------------------
__global__ void k_fill(const int* __restrict__ src, const int* __restrict__ dst) {
    int q = blockIdx.x * blockDim.x + threadIdx.x;
    if (q < N_EDGES / 4) {
        int4 s = __ldg(&((const int4*)src)[q]);
        int4 d = __ldg(&((const int4*)dst)[q]);
        g_srcs[atomicAdd(&g_cursor[d.x], 1)] = s.x;
        g_srcs[atomicAdd(&g_cursor[d.y], 1)] = s.y;
        g_srcs[atomicAdd(&g_cursor[d.z], 1)] = s.z;
        g_srcs[atomicAdd(&g_cursor[d.w], 1)] = s.w;
    }
}

// ------------------------------------------------------------------
// K5: gather-aggregate. One warp per node; lane owns a float4 chunk.
// unroll-8 to hide L2 latency.
// ------------------------------------------------------------------
__global__ void k_aggregate(const float* __restrict__ feat) {
    int gw   = (blockIdx.x * blockDim.x + threadIdx.x) >> 5;
    int lane = threadIdx.x & 31;
    if (gw >= N_NODES) return;

    const float4* f4 = (const float4*)feat;
    float4 acc = __ldg(&f4[(size_t)gw * 32 + lane]);   // self loop

    int j = g_off[gw];
    const int e = g_off[gw + 1];
    for (; j + 7 < e; j += 8) {
        int u0 = g_srcs[j];     int u1 = g_srcs[j + 1];
        int u2 = g_srcs[j + 2]; int u3 = g_srcs[j + 3];
        int u4 = g_srcs[j + 4]; int u5 = g_srcs[j + 5];
        int u6 = g_srcs[j + 6]; int u7 = g_srcs[j + 7];
        float4 x0 = __ldg(&f4[(size_t)u0 * 32 + lane]);
        float4 x1 = __ldg(&f4[(size_t)u1 * 32 + lane]);
        float4 x2 = __ldg(&f4[(size_t)u2 * 32 + lane]);
        float4 x3 = __ldg(&f4[(size_t)u3 * 32 + lane]);
        float4 x4 = __ldg(&f4[(size_t)u4 * 32 + lane]);
        float4 x5 = __ldg(&f4[(size_t)u5 * 32 + lane]);
        float4 x6 = __ldg(&f4[(size_t)u6 * 32 + lane]);
        float4 x7 = __ldg(&f4[(size_t)u7 * 32 + lane]);
        acc.x += ((x0.x + x1.x) + (x2.x + x3.x)) + ((x4.x + x5.x) + (x6.x + x7.x));
        acc.y += ((x0.y + x1.y) + (x2.y + x3.y)) + ((x4.y + x5.y) + (x6.y + x7.y));
        acc.z += ((x0.z + x1.z) + (x2.z + x3.z)) + ((x4.z + x5.z) + (x6.z + x7.z));
        acc.w += ((x0.w + x1.w) + (x2.w + x3.w)) + ((x4.w + x5.w) + (x6.w + x7.w));
    }
    for (; j + 3 < e; j += 4) {
        int u0 = g_srcs[j];     int u1 = g_srcs[j + 1];
        int u2 = g_srcs[j + 2]; int u3 = g_srcs[j + 3];
        float4 x0 = __ldg(&f4[(size_t)u0 * 32 + lane]);
        float4 x1 = __ldg(&f4[(size_t)u1 * 32 + lane]);
        float4 x2 = __ldg(&f4[(size_t)u2 * 32 + lane]);
        float4 x3 = __ldg(&f4[(size_t)u3 * 32 + lane]);
        acc.x += (x0.x + x1.x) + (x2.x + x3.x);
        acc.y += (x0.y + x1.y) + (x2.y + x3.y);
        acc.z += (x0.z + x1.z) + (x2.z + x3.z);
        acc.w += (x0.w + x1.w) + (x2.w + x3.w);
    }
    for (; j < e; j++) {
        int u = g_srcs[j];
        float4 x = __ldg(&f4[(size_t)u * 32 + lane]);
        acc.x += x.x; acc.y += x.y; acc.z += x.z; acc.w += x.w;
    }
    ((float4*)g_h)[(size_t)gw * 32 + lane] = acc;
}

// ------------------------------------------------------------------
// tf32 round-to-nearest (unbiased; raw truncation would bias the dot ~1e-3)
// ------------------------------------------------------------------
__device__ __forceinline__ float tf32r(float x) {
    unsigned u;
    asm("cvt.rna.tf32.f32 %0, %1;" : "=r"(u) : "f"(x));
    return __uint_as_float(u);
}

// ------------------------------------------------------------------
// K6: tf32 tensor-core GEMM  out[M,256] = h[M,128] @ W[128,256] + bias
// CTA 128x128 tile, 256 thr = 8 warps (4M x 2N), warp tile 32x64 via
// mma.sync.m16n8k8 tf32 (2 m-atoms x 8 n-atoms). K chunked by 32, fp32 accum.
// Smem padded: As stride 36, Bs stride 136 -> conflict-free fragment LDS.
// Register-prefetch pipeline on global loads retained.
// ------------------------------------------------------------------
__global__ void __launch_bounds__(256) k_gemm(const float* __restrict__ W,
                                              const float* __restrict__ bias,
                                              float* __restrict__ out) {
    __shared__ __align__(16) float As[128][36];   // [m][k], pad 4
    __shared__ __align__(16) float Bs[32][136];   // [k][n], pad 8

    const int tid  = threadIdx.x;
    const int lane = tid & 31;
    const int wid  = tid >> 5;            // 0..7
    const int wm   = (wid & 3) * 32;      // warp m offset in tile
    const int wn   = (wid >> 2) * 64;     // warp n offset in tile
    const int grp  = lane >> 2;           // 0..7
    const int tig  = lane & 3;            // 0..3
    const int m0   = blockIdx.y * 128;
    const int n0   = blockIdx.x * 128;

    float c[2][8][4];
    #pragma unroll
    for (int ma = 0; ma < 2; ma++)
        #pragma unroll
        for (int na = 0; na < 8; na++)
            #pragma unroll
            for (int r = 0; r < 4; r++) c[ma][na][r] = 0.f;

    // ---- prologue: fetch K-chunk 0 into registers ----
    float4 pa[4], pb[4];
    #pragma unroll
    for (int i = 0; i < 4; i++) {
        int l  = tid + 256 * i;
        int r  = l >> 3, ks = l & 7;        // A: 128 rows x 8 float4
        int row = m0 + r;
        pa[i] = (row < N_NODES)
              ? *(const float4*)&g_h[(size_t)row * 128 + ks * 4]
              : make_float4(0.f, 0.f, 0.f, 0.f);
        int k  = l >> 5, cs = l & 31;       // B: 32 k x 32 float4
        pb[i] = __ldg((const float4*)&W[(size_t)k * OUT_F + n0 + cs * 4]);
    }

    #pragma unroll
    for (int kk = 0; kk < 128; kk += 32) {
        // stage prefetched chunk into smem, rounding to tf32 (rna)
        #pragma unroll
        for (int i = 0; i < 4; i++) {
            int l = tid + 256 * i;
            float4 va = make_float4(tf32r(pa[i].x), tf32r(pa[i].y),
                                    tf32r(pa[i].z), tf32r(pa[i].w));
            float4 vb = make_float4(tf32r(pb[i].x), tf32r(pb[i].y),
                                    tf32r(pb[i].z), tf32r(pb[i].w));
            *(float4*)&As[l >> 3][(l & 7) * 4]  = va;
            *(float4*)&Bs[l >> 5][(l & 31) * 4] = vb;
        }
        __syncthreads();

        // prefetch next chunk (drains under the mma stream)
        if (kk + 32 < 128) {
            #pragma unroll
            for (int i = 0; i < 4; i++) {
                int l  = tid + 256 * i;
                int r  = l >> 3, ks = l & 7;
                int row = m0 + r;
                pa[i] = (row < N_NODES)
                      ? *(const float4*)&g_h[(size_t)row * 128 + (kk + 32) + ks * 4]
                      : make_float4(0.f, 0.f, 0.f, 0.f);
                int k  = l >> 5, cs = l & 31;
                pb[i] = __ldg((const float4*)&W[(size_t)(kk + 32 + k) * OUT_F + n0 + cs * 4]);
            }
        }

        // compute: 4 k-steps of 8
        #pragma unroll
        for (int ks = 0; ks < 4; ks++) {
            const int k0 = ks * 8;
            unsigned a[2][4], b[8][2];
            #pragma unroll
            for (int ma = 0; ma < 2; ma++) {
                int row = wm + ma * 16 + grp;
                a[ma][0] = __float_as_uint(As[row][k0 + tig]);
                a[ma][1] = __float_as_uint(As[row + 8][k0 + tig]);
                a[ma][2] = __float_as_uint(As[row][k0 + tig + 4]);
                a[ma][3] = __float_as_uint(As[row + 8][k0 + tig + 4]);
            }
            #pragma unroll
            for (int na = 0; na < 8; na++) {
                int coln = wn + na * 8 + grp;
                b[na][0] = __float_as_uint(Bs[k0 + tig][coln]);
                b[na][1] = __float_as_uint(Bs[k0 + tig + 4][coln]);
            }
            #pragma unroll
            for (int ma = 0; ma < 2; ma++)
                #pragma unroll
                for (int na = 0; na < 8; na++)
                    asm volatile(
                        "mma.sync.aligned.m16n8k8.row.col.f32.tf32.tf32.f32 "
                        "{%0,%1,%2,%3}, {%4,%5,%6,%7}, {%8,%9}, {%0,%1,%2,%3};"
                        : "+f"(c[ma][na][0]), "+f"(c[ma][na][1]),
                          "+f"(c[ma][na][2]), "+f"(c[ma][na][3])
                        : "r"(a[ma][0]), "r"(a[ma][1]), "r"(a[ma][2]), "r"(a[ma][3]),
                          "r"(b[na][0]), "r"(b[na][1]));
        }
        __syncthreads();
    }

    // epilogue: + bias, float2 stores
    #pragma unroll
    for (int ma = 0; ma < 2; ma++) {
        #pragma unroll
        for (int na = 0; na < 8; na++) {
            int col  = n0 + wn + na * 8 + 2 * tig;
            float2 bv = *(const float2*)&bias[col];
            int row  = m0 + wm + ma * 16 + grp;
            if (row < N_NODES) {
                float2 v = make_float2(c[ma][na][0] + bv.x, c[ma][na][1] + bv.y);
                *(float2*)&out[(size_t)row * OUT_F + col] = v;
            }
            int row2 = row + 8;
            if (row2 < N_NODES) {
                float2 v = make_float2(c[ma][na][2] + bv.x, c[ma][na][3] + bv.y);
                *(float2*)&out[(size_t)row2 * OUT_F + col] = v;
            }
        }
    }
}

// ------------------------------------------------------------------
extern "C" void kernel_launch(void* const* d_in, const int* in_sizes, int n_in,
                              void* d_out, int out_size) {
    const float* features = (const float*)d_in[0];
    const int*   src      = (const int*)d_in[1];
    const int*   dst      = (const int*)d_in[2];
    const float* weight   = (const float*)d_in[3];
    const float* bias     = (const float*)d_in[4];
    float*       out      = (float*)d_out;

    k_count      <<<(N_EDGES / 4 + 255) / 256, 256>>>(dst);
    k_scan_blocks<<<N_SCAN_BLKS, SCAN_BLK>>>();
    k_scan_add   <<<N_SCAN_BLKS, SCAN_BLK>>>();
    k_fill       <<<(N_EDGES / 4 + 255) / 256, 256>>>(src, dst);
    k_aggregate  <<<(N_NODES * 32 + 255) / 256, 256>>>(features);

    dim3 ggrid(OUT_F / 128, (N_NODES + 127) / 128);   // (2, 782)
    k_gemm<<<ggrid, 256>>>(weight, bias, out);
}